// round 10
// baseline (speedup 1.0000x reference)
#include <cuda_runtime.h>
#include <cstdint>

// 64 steps of diffusion-advection on a 1024x1024 periodic grid -> (T,3,H,W)
// fp32 RGB, ONE persistent kernel.
//
//  - r channel of frame s == u_{s+1} exactly (clipped); frames carry state.
//  - Per-row flags: bar + st.release.gpu publish / ld.acquire.gpu spin.
//  - g/b channels (2/3 of traffic, never read) leave through the ASYNC PROXY:
//    STS to parity smem row buffers, then cp.async.bulk.global.shared::cta.
//    st.release.gpu does NOT order async-proxy writes, so the g/b drain is
//    fully off the synchronization chain; buffer reuse is gated by
//    cp.async.bulk.wait_group.read.
//  - 1024 blocks x 256 threads, 1 row/block, u in registers. launch_bounds
//    (256,7) -> <=36 regs -> 148*7=1036 resident slots >= 1024 (spin-safe).

#define HH 1024
#define WW 1024
#define HW (HH * WW)

#define DT     0.1f
#define ALPHA  0.05f
#define V_X    0.1f
// V_Y == 0 -> du_dy term vanishes.

#define NB 1024
#define FS 32                 // flag stride in ints (128 B)

__device__ int g_flags[NB * FS];

__global__ void reset_flags_kernel() {
    const int i = blockIdx.x * blockDim.x + threadIdx.x;   // 0..NB-1
    g_flags[i * FS] = 0;
}

__device__ __forceinline__ int ld_acq(const int* p) {
    int v;
    asm volatile("ld.acquire.gpu.global.b32 %0, [%1];"
                 : "=r"(v) : "l"(p) : "memory");
    return v;
}
__device__ __forceinline__ void st_rel(int* p, int v) {
    asm volatile("st.release.gpu.global.b32 [%0], %1;"
                 :: "l"(p), "r"(v) : "memory");
}
__device__ __forceinline__ void bulk_store(void* gdst, const void* ssrc,
                                           int bytes) {
    uint32_t saddr = (uint32_t)__cvta_generic_to_shared(ssrc);
    asm volatile("cp.async.bulk.global.shared::cta.bulk_group [%0], [%1], %2;"
                 :: "l"(gdst), "r"(saddr), "r"(bytes) : "memory");
}

__global__ __launch_bounds__(256, 7)
void physics_persistent_kernel(const float* __restrict__ u_init,
                               float* __restrict__ frames,
                               int n_frames)
{
    __shared__ float  sEdge[2][2][8];      // [parity][first/last][warp]
    __shared__ float4 bufG[2][256];        // parity row buffers, 8 KB
    __shared__ float4 bufB[2][256];        // 8 KB

    const int y    = blockIdx.x;           // owned row
    const int c4   = threadIdx.x;          // float4 column 0..255
    const int lane = c4 & 31;
    const int wid  = c4 >> 5;
    const int ym1  = (y - 1) & (HH - 1);
    const int yp1  = (y + 1) & (HH - 1);

    const int idx  = (y   << 8) + c4;      // float4 index within a channel
    const int idxu = (ym1 << 8) + c4;
    const int idxd = (yp1 << 8) + c4;

    int*       flag_self = &g_flags[y   * FS];
    const int* flag_up   = &g_flags[ym1 * FS];
    const int* flag_dn   = &g_flags[yp1 * FS];

    float4 u = ((const float4*)u_init)[idx];   // u_s for own row
    const float* src = u_init;                 // where u_s lives (r of s-1)
    float*       fr  = frames;                 // frame s base

    if (lane == 0)  sEdge[0][0][wid] = u.x;
    if (lane == 31) sEdge[0][1][wid] = u.w;
    __syncthreads();

    for (int s = 0; s < n_frames; ++s) {
        if (s > 0) {
            while (ld_acq(flag_up) < s) { }
            while (ld_acq(flag_dn) < s) { }
        }

        const float4* src4 = (const float4*)src;
        const float4 hu = __ldcg(&src4[idxu]);
        const float4 hd = __ldcg(&src4[idxd]);

        const int par = s & 1;
        const float lwS = sEdge[par][1][(wid - 1) & 7];
        const float rxS = sEdge[par][0][(wid + 1) & 7];

        float lw = __shfl_up_sync(0xffffffffu, u.w, 1);
        float rx = __shfl_down_sync(0xffffffffu, u.x, 1);
        if (lane == 0)  lw = lwS;
        if (lane == 31) rx = rxS;

        const float uc[4] = {u.x,  u.y,  u.z,  u.w};
        const float ul[4] = {lw,   u.x,  u.y,  u.z};
        const float ur[4] = {u.y,  u.z,  u.w,  rx};
        const float uu[4] = {hu.x, hu.y, hu.z, hu.w};
        const float ud[4] = {hd.x, hd.y, hd.z, hd.w};

        float4 n;
        float* np = &n.x;
        #pragma unroll
        for (int i = 0; i < 4; ++i) {
            const float lap = ul[i] + ur[i] + uu[i] + ud[i] - 4.0f * uc[i];
            float v = uc[i] + DT * (ALPHA * lap - V_X * (uc[i] - ul[i]));
            np[i] = fminf(fmaxf(v, 0.0f), 1.0f);
        }

        // r channel (the only data anyone reads back).
        ((float4*)fr)[idx] = n;

        // Stage next step's warp edges (other parity slot).
        if (lane == 0)  sEdge[par ^ 1][0][wid] = n.x;
        if (lane == 31) sEdge[par ^ 1][1][wid] = n.w;

        __syncthreads();                         // bar1: r stores + edges
        if (c4 == 0) {
            st_rel(flag_self, s + 1);            // publish (covers r only)
            // Free buf[par]: group from step s-2 must have read its source.
            asm volatile("cp.async.bulk.wait_group.read 1;" ::: "memory");
        }
        __syncthreads();                         // bar2: buffer free

        float4 t;
        t.x = n.x * 0.5f; t.y = n.y * 0.5f;
        t.z = n.z * 0.5f; t.w = n.w * 0.5f;
        bufG[par][c4] = t;
        t.x = 1.0f - n.x; t.y = 1.0f - n.y;
        t.z = 1.0f - n.z; t.w = 1.0f - n.w;
        bufB[par][c4] = t;
        __syncthreads();                         // bar3: STS visible

        if (c4 == 0) {
            asm volatile("fence.proxy.async.shared::cta;" ::: "memory");
            bulk_store(fr + HW     + (y << 10), &bufG[par][0], WW * 4);
            bulk_store(fr + 2 * HW + (y << 10), &bufB[par][0], WW * 4);
            asm volatile("cp.async.bulk.commit_group;" ::: "memory");
        }

        u   = n;
        src = fr;          // r channel of frame s == u_{s+1}
        fr += 3 * HW;
    }
}

extern "C" void kernel_launch(void* const* d_in, const int* in_sizes, int n_in,
                              void* d_out, int out_size) {
    const float* init = (const float*)d_in[0];
    float* out = (float*)d_out;
    const int n_frames = out_size / (3 * HW);

    reset_flags_kernel<<<NB / 256, 256>>>();
    physics_persistent_kernel<<<NB, 256>>>(init, out, n_frames);
}